// round 15
// baseline (speedup 1.0000x reference)
#include <cuda_runtime.h>
#include <cuda_fp16.h>
#include <math.h>
#include <stdint.h>

#define BB 64
#define LDN 512
#define LQN 128
#define DDIM 512
#define KU   (DDIM/2)   // 256 uints (half2) per feature row
#define KG   320        // graph-part row width in uints: (512+128)/2
#define RSH  20         // smem row stride in uints: 16 data + 4 pad (conflict-free)
#define STAGE_B 15360u  // bytes per stage: A 128 rows (10240) + B 64 rows (5120)
#define SMEM_DYN (3 * 15360)

// ---------------- fp16 buffers (uint32 = half2, pairs along K) ----------------
__device__ uint32_t g_xdh[(size_t)BB*LDN*KU];    // d state (step input)
__device__ uint32_t g_xqh[(size_t)BB*LQN*KU];
__device__ uint32_t g_xdh2[(size_t)BB*LDN*KU];   // d state (next step)
__device__ uint32_t g_xqh2[(size_t)BB*LQN*KU];
__device__ uint32_t g_adh[(size_t)BB*LDN*KG];    // inv⊙[dd | dq] per d-row
__device__ uint32_t g_aqh[(size_t)BB*LQN*KG];    // inv⊙[qq | qd] per q-row
__device__ uint32_t g_bdh[(size_t)BB*DDIM*KG];   // [dd_info(256u) | dq_info(64u)] per n
__device__ uint32_t g_bqh[(size_t)BB*DDIM*KG];   // [qq_info(64u)  | qd_info(256u)] per n
__device__ uint32_t g_wh[5][(size_t)DDIM*KU];    // self, dd, qd, qq, dq
__device__ float g_dw[BB*LDN];
__device__ float g_qw[BB*LQN];

// ---------------- helpers ----------------
__device__ __forceinline__ uint32_t pk(float lo, float hi) {
    uint32_t u;
    asm("cvt.rn.f16x2.f32 %0, %1, %2;" : "=r"(u) : "f"(hi), "f"(lo));
    return u;
}
__device__ __forceinline__ void mma16(float* c, const uint32_t* a, const uint32_t* b) {
    asm volatile(
        "mma.sync.aligned.m16n8k16.row.col.f32.f16.f16.f32 "
        "{%0,%1,%2,%3}, {%4,%5,%6,%7}, {%8,%9}, {%0,%1,%2,%3};"
        : "+f"(c[0]), "+f"(c[1]), "+f"(c[2]), "+f"(c[3])
        : "r"(a[0]), "r"(a[1]), "r"(a[2]), "r"(a[3]), "r"(b[0]), "r"(b[1]));
}
__device__ __forceinline__ void ldm4(uint32_t* r, uint32_t addr) {
    asm volatile("ldmatrix.sync.aligned.m8n8.x4.shared.b16 {%0,%1,%2,%3}, [%4];"
                 : "=r"(r[0]), "=r"(r[1]), "=r"(r[2]), "=r"(r[3]) : "r"(addr));
}
__device__ __forceinline__ uint32_t smem_u32(const void* p) {
    uint32_t a;
    asm("{ .reg .u64 t; cvta.to.shared.u64 t, %1; cvt.u32.u64 %0, t; }" : "=r"(a) : "l"(p));
    return a;
}
__device__ __forceinline__ void cp16(uint32_t daddr, const uint32_t* g) {
    asm volatile("cp.async.cg.shared.global [%0], [%1], 16;"
                 :: "r"(daddr), "l"(__cvta_generic_to_global((void*)g)));
}
__device__ __forceinline__ void cpcommit() { asm volatile("cp.async.commit_group;"); }
__device__ __forceinline__ void cpwait0()  { asm volatile("cp.async.wait_group 0;"); }
__device__ __forceinline__ void cpwait1()  { asm volatile("cp.async.wait_group 1;"); }

// stage one (128-row A, 64-row B) x 32half tile pair into 3-stage ring via cp.async
__device__ __forceinline__ void issue3(uint32_t sb, int buf,
                                       const uint32_t* Asrc, int sA,
                                       const uint32_t* Bsrc, int sB,
                                       int kkU, int t) {
    uint32_t base = sb + (uint32_t)buf * STAGE_B;
    #pragma unroll
    for (int s = 0; s < 3; s++) {
        int idx = s * 256 + t;            // 768 16B copies: 512 A + 256 B
        int row = idx >> 2, c4 = idx & 3;
        if (row < 128) {
            uint32_t off = (uint32_t)((row * RSH + c4 * 4) * 4);
            cp16(base + off, Asrc + (size_t)row * sA + kkU + c4 * 4);
        } else {
            int r = row - 128;
            uint32_t off = 10240u + (uint32_t)((r * RSH + c4 * 4) * 4);
            cp16(base + off, Bsrc + (size_t)r * sB + kkU + c4 * 4);
        }
    }
    cpcommit();
}

// ldmatrix-based 32-K chunk compute (warp tile 32x32: 2 A frags x 2 B frags, 8 MMAs/kb)
__device__ __forceinline__ void compute_chunk(uint32_t aBase, uint32_t bBase,
                                              uint32_t so, float acc[2][4][4]) {
    #pragma unroll
    for (int kb = 0; kb < 2; kb++) {
        uint32_t a[2][4], bb[2][4];
        ldm4(a[0], aBase + so + (uint32_t)((kb * 8) * 4));
        ldm4(a[1], aBase + so + (uint32_t)((16 * RSH + kb * 8) * 4));
        ldm4(bb[0], bBase + so + (uint32_t)((kb * 8) * 4));
        ldm4(bb[1], bBase + so + (uint32_t)((16 * RSH + kb * 8) * 4));
        uint32_t b2[4][2] = {{bb[0][0], bb[0][2]}, {bb[0][1], bb[0][3]},
                             {bb[1][0], bb[1][2]}, {bb[1][1], bb[1][3]}};
        #pragma unroll
        for (int i = 0; i < 2; i++)
            #pragma unroll
            for (int j = 0; j < 4; j++)
                mma16(acc[i][j], a[i], b2[j]);
    }
}

// ---------------- fused prep: weight cvt + graph nb-cvt + state cvt, one launch ----------------
__device__ __forceinline__ void nbrow(const int* A1, const int* A2, int K1, int K2,
                                      int w, int lane, uint32_t* outA) {
    const int2* r1 = (const int2*)(A1 + (size_t)w * K1);
    const int2* r2 = (const int2*)(A2 + (size_t)w * K2);
    int Ku1 = K1 >> 1, Kt = (K1 + K2) >> 1;
    int s = 0;
    for (int u = lane; u < Ku1; u += 32) { int2 v = r1[u]; s += v.x + v.y; }
    for (int u = lane; u < Kt - Ku1; u += 32) { int2 v = r2[u]; s += v.x + v.y; }
    #pragma unroll
    for (int o = 16; o; o >>= 1) s += __shfl_xor_sync(0xFFFFFFFFu, s, o);
    float inv = 1.0f / ((s < 1) ? 1.0f : (float)s);
    uint32_t* orow = outA + (size_t)w * Kt;
    for (int u = lane; u < Kt; u += 32) {
        int2 v = (u < Ku1) ? r1[u] : r2[u - Ku1];
        orow[u] = pk(inv * (float)v.x, inv * (float)v.y);
    }
}

__global__ void prep_all(const float* __restrict__ w0, const float* __restrict__ w1,
                         const float* __restrict__ w2, const float* __restrict__ w3,
                         const float* __restrict__ w4, uint32_t* __restrict__ wdst,
                         const int* __restrict__ dd, const int* __restrict__ dq,
                         const int* __restrict__ qq, const int* __restrict__ qd,
                         uint32_t* __restrict__ outAd, uint32_t* __restrict__ outAq,
                         const float* __restrict__ dsrc, const float* __restrict__ qsrc,
                         uint32_t* __restrict__ xdh, uint32_t* __restrict__ xqh) {
    int bx = blockIdx.x;
    int t = threadIdx.x;
    if (bx < 320) {
        for (int i = bx * 256 + t; i < 5 * 65536; i += 320 * 256) {
            int which = i >> 16, off = i & 65535;
            const float* w = which == 0 ? w0 : which == 1 ? w1 : which == 2 ? w2
                           : which == 3 ? w3 : w4;
            float4 v = *(const float4*)(w + (size_t)off * 4);
            uint2 o = {pk(v.x, v.y), pk(v.z, v.w)};
            *(uint2*)(wdst + (size_t)i * 2) = o;
        }
    } else if (bx < 320 + 5120) {
        int w = (((bx - 320) * 256 + t)) >> 5;
        int lane = t & 31;
        int nd = BB * LDN;
        if (w < nd) nbrow(dd, dq, LDN, LQN, w, lane, outAd);
        else {
            w -= nd;
            if (w < BB * LQN) nbrow(qq, qd, LQN, LDN, w, lane, outAq);
        }
    } else {
        const int n4d = BB * LDN * DDIM / 4;
        const int n4t = n4d + BB * LQN * DDIM / 4;
        for (int i = (bx - 5440) * 256 + t; i < n4t; i += 2048 * 256) {
            const float* s;
            uint32_t* d;
            int off;
            if (i < n4d) { s = dsrc; d = xdh; off = i; }
            else         { s = qsrc; d = xqh; off = i - n4d; }
            float4 v = *(const float4*)(s + (size_t)off * 4);
            uint2 o = {pk(v.x, v.y), pk(v.z, v.w)};
            *(uint2*)(d + (size_t)off * 2) = o;
        }
    }
}

// ---------------- merged node weights: sigmoid(x . W_nw + b_nw) for d and q ----------------
__global__ void nw2(const uint32_t* __restrict__ xd, const uint32_t* __restrict__ xq,
                    const float* __restrict__ Wnw, const float* __restrict__ bnw,
                    float* __restrict__ dw, float* __restrict__ qw,
                    float* __restrict__ odw, float* __restrict__ oqw) {
    int w = (blockIdx.x * blockDim.x + threadIdx.x) >> 5;
    int lane = threadIdx.x & 31;
    const int nd = BB * LDN;
    const uint32_t* x;
    float *wbuf, *outw;
    int b, l, stride_b;
    if (w < nd) {
        x = xd + (size_t)w * KU; wbuf = dw; outw = odw;
        b = w >> 9; l = w & (LDN - 1); stride_b = 2 * LDN;
    } else {
        w -= nd;
        if (w >= BB * LQN) return;
        x = xq + (size_t)w * KU; wbuf = qw; outw = oqw;
        b = w >> 7; l = w & (LQN - 1); stride_b = 2 * LQN;
    }
    float s = 0.0f;
    #pragma unroll 4
    for (int u = lane; u < KU; u += 32) {
        float2 h = __half22float2(*(const __half2*)&x[u]);
        s += h.x * Wnw[2 * u] + h.y * Wnw[2 * u + 1];
    }
    #pragma unroll
    for (int o = 16; o; o >>= 1) s += __shfl_xor_sync(0xFFFFFFFFu, s, o);
    if (lane == 0) {
        float z = s + bnw[0];
        float v = 1.0f / (1.0f + expf(-z));
        wbuf[w] = v;
        outw[(size_t)b * stride_b + l] = v;
    }
}

// ---------------- fused info GEMM (all 4 weights, both node sets, one launch) ----------------
// blockIdx.x: 0-7 dd_info(j0=bx*64), 8-15 qd_info, 16-17 qq_info, 18-19 dq_info
__global__ void __launch_bounds__(256, 4)
gemm_info2(const uint32_t* __restrict__ wh_dd, const uint32_t* __restrict__ wh_qd,
           const uint32_t* __restrict__ wh_qq, const uint32_t* __restrict__ wh_dq,
           const uint32_t* __restrict__ xd, const uint32_t* __restrict__ xq,
           const float* __restrict__ dw, const float* __restrict__ qw,
           uint32_t* __restrict__ bdh, uint32_t* __restrict__ bqh) {
    extern __shared__ uint32_t smd[];
    uint32_t sb = smem_u32(smd);
    int t = threadIdx.x;
    int bx = blockIdx.x;
    int n0 = blockIdx.y * 128;
    int z = blockIdx.z;

    const uint32_t *Wsel, *X;
    const float* ws;
    uint32_t* ot;
    int L, j0;
    if (bx < 8)       { Wsel = wh_dd; X = xd; ws = dw; ot = bdh;       L = LDN; j0 = bx * 64; }
    else if (bx < 16) { Wsel = wh_qd; X = xd; ws = dw; ot = bqh + 64;  L = LDN; j0 = (bx - 8) * 64; }
    else if (bx < 18) { Wsel = wh_qq; X = xq; ws = qw; ot = bqh;       L = LQN; j0 = (bx - 16) * 64; }
    else              { Wsel = wh_dq; X = xq; ws = qw; ot = bdh + 256; L = LQN; j0 = (bx - 18) * 64; }

    const uint32_t* Ab = Wsel + (size_t)n0 * KU;
    const uint32_t* Bb = X + ((size_t)z * L + j0) * KU;
    ws += (size_t)z * L;
    ot += (size_t)z * DDIM * KG;

    int lane = t & 31, g = lane >> 2, tg = lane & 3;
    int wid = t >> 5;
    int wy = wid & 3, wx = wid >> 2;   // 4 M-groups x 2 N-groups, warp tile 32x32
    uint32_t aBase = sb + (uint32_t)(((wy * 32 + (lane & 15)) * RSH + (lane >> 4) * 4) * 4);
    uint32_t bBase = sb + 10240u +
                     (uint32_t)(((wx * 32 + (lane & 15)) * RSH + (lane >> 4) * 4) * 4);

    float acc[2][4][4];
    #pragma unroll
    for (int i = 0; i < 2; i++)
        #pragma unroll
        for (int j = 0; j < 4; j++)
            #pragma unroll
            for (int k = 0; k < 4; k++) acc[i][j][k] = 0.0f;

    issue3(sb, 0, Ab, KU, Bb, KU, 0, t);
    issue3(sb, 1, Ab, KU, Bb, KU, 16, t);
    for (int c = 0; c < 16; c++) {
        if (c + 1 < 16) cpwait1(); else cpwait0();
        __syncthreads();
        if (c + 2 < 16) issue3(sb, (c + 2) % 3, Ab, KU, Bb, KU, (c + 2) * 16, t);
        compute_chunk(aBase, bBase, (uint32_t)(c % 3) * STAGE_B, acc);
    }

    #pragma unroll
    for (int i = 0; i < 2; i++) {
        int R0 = n0 + wy * 32 + i * 16 + g;
        int R1 = R0 + 8;
        #pragma unroll
        for (int j = 0; j < 4; j++) {
            int C = j0 + wx * 32 + j * 8 + 2 * tg;
            float2 s = *(const float2*)&ws[C];
            ot[(size_t)R0 * KG + (C >> 1)] = pk(acc[i][j][0] * s.x, acc[i][j][1] * s.y);
            ot[(size_t)R1 * KG + (C >> 1)] = pk(acc[i][j][2] * s.x, acc[i][j][3] * s.y);
        }
    }
}

// ---------------- fused message+self GEMM (d and q sides in one launch) ----------------
// blockIdx.y 0-3: d-side row blocks; 4: q-side (M=128). blockIdx.x: n-tile of 64.
__global__ void __launch_bounds__(256, 4)
gemm_msg2(const uint32_t* __restrict__ adh, const uint32_t* __restrict__ aqh,
          const uint32_t* __restrict__ xd, const uint32_t* __restrict__ xq,
          const uint32_t* __restrict__ bdh, const uint32_t* __restrict__ bqh,
          const uint32_t* __restrict__ wself, const float* __restrict__ bias,
          float* __restrict__ outd, uint32_t* __restrict__ outHd,
          float* __restrict__ outq, uint32_t* __restrict__ outHq) {
    int z = blockIdx.z;
    int by = blockIdx.y;
    const uint32_t *Ag, *Xh, *Bg;
    float* out;
    uint32_t* outH;
    int M, r0;
    if (by < 4) { Ag = adh; Xh = xd; Bg = bdh; out = outd; outH = outHd; M = LDN; r0 = by * 128; }
    else        { Ag = aqh; Xh = xq; Bg = bqh; out = outq; outH = outHq; M = LQN; r0 = 0; }
    Ag += (size_t)z * M * KG;
    Xh += (size_t)z * M * KU;
    Bg += (size_t)z * DDIM * KG;
    if (out)  out  += (size_t)z * M * DDIM;
    if (outH) outH += (size_t)z * M * KU;

    extern __shared__ uint32_t smd[];
    uint32_t sb = smem_u32(smd);
    int t = threadIdx.x;
    int c0 = blockIdx.x * 64;
    const uint32_t* Ab1 = Ag + (size_t)r0 * KG;
    const uint32_t* Ab2 = Xh + (size_t)r0 * KU;
    const uint32_t* Bb1 = Bg + (size_t)c0 * KG;
    const uint32_t* Bb2 = wself + (size_t)c0 * KU;

    int lane = t & 31, g = lane >> 2, tg = lane & 3;
    int wid = t >> 5;
    int wy = wid & 3, wx = wid >> 2;   // 4 M-groups x 2 N-groups, warp tile 32x32
    uint32_t aBase = sb + (uint32_t)(((wy * 32 + (lane & 15)) * RSH + (lane >> 4) * 4) * 4);
    uint32_t bBase = sb + 10240u +
                     (uint32_t)(((wx * 32 + (lane & 15)) * RSH + (lane >> 4) * 4) * 4);

    float acc[2][4][4];
    #pragma unroll
    for (int i = 0; i < 2; i++)
        #pragma unroll
        for (int j = 0; j < 4; j++)
            #pragma unroll
            for (int k = 0; k < 4; k++) acc[i][j][k] = 0.0f;

    const int nch = 36;  // 20 graph chunks + 16 feature chunks
    issue3(sb, 0, Ab1, KG, Bb1, KG, 0, t);
    issue3(sb, 1, Ab1, KG, Bb1, KG, 16, t);
    for (int c = 0; c < nch; c++) {
        if (c + 1 < nch) cpwait1(); else cpwait0();
        __syncthreads();
        if (c + 2 < nch) {
            int kkU = (c + 2) * 16;
            if (kkU < KG) issue3(sb, (c + 2) % 3, Ab1, KG, Bb1, KG, kkU, t);
            else          issue3(sb, (c + 2) % 3, Ab2, KU, Bb2, KU, kkU - KG, t);
        }
        compute_chunk(aBase, bBase, (uint32_t)(c % 3) * STAGE_B, acc);
    }

    #pragma unroll
    for (int i = 0; i < 2; i++) {
        int R0 = r0 + wy * 32 + i * 16 + g;
        int R1 = R0 + 8;
        #pragma unroll
        for (int j = 0; j < 4; j++) {
            int C = c0 + wx * 32 + j * 8 + 2 * tg;
            float2 bz = *(const float2*)&bias[C];
            float2 v0, v1;
            v0.x = fmaxf(acc[i][j][0] + bz.x, 0.0f);
            v0.y = fmaxf(acc[i][j][1] + bz.y, 0.0f);
            v1.x = fmaxf(acc[i][j][2] + bz.x, 0.0f);
            v1.y = fmaxf(acc[i][j][3] + bz.y, 0.0f);
            if (out) {
                *(float2*)&out[(size_t)R0 * DDIM + C] = v0;
                *(float2*)&out[(size_t)R1 * DDIM + C] = v1;
            }
            if (outH) {
                outH[(size_t)R0 * KU + (C >> 1)] = pk(v0.x, v0.y);
                outH[(size_t)R1 * KU + (C >> 1)] = pk(v1.x, v1.y);
            }
        }
    }
}

// ---------------- host orchestration ----------------
extern "C" void kernel_launch(void* const* d_in, const int* in_sizes, int n_in,
                              void* d_out_, int out_size) {
    const float* d_node = (const float*)d_in[0];
    const float* q_node = (const float*)d_in[1];
    const int*   qq     = (const int*)d_in[2];
    const int*   dq     = (const int*)d_in[3];
    const int*   dd     = (const int*)d_in[4];
    const int*   qd     = (const int*)d_in[5];
    const float* W_nw   = (const float*)d_in[6];
    const float* b_nw   = (const float*)d_in[7];
    const float* W_self = (const float*)d_in[8];
    const float* b_self = (const float*)d_in[9];
    const float* W_dd   = (const float*)d_in[10];
    const float* W_qq   = (const float*)d_in[11];
    const float* W_dq   = (const float*)d_in[12];
    const float* W_qd   = (const float*)d_in[13];

    float* out = (float*)d_out_;
    float* out_dnode = out;
    float* out_qnode = out + (size_t)BB * LDN * DDIM;
    float* out_dw    = out_qnode + (size_t)BB * LQN * DDIM;
    float* out_qw    = out_dw + (size_t)BB * 2 * LDN;

    float *p_dw, *p_qw;
    uint32_t *p_xdh, *p_xqh, *p_xdh2, *p_xqh2, *p_adh, *p_aqh, *p_bdh, *p_bqh, *p_wh;
    cudaGetSymbolAddress((void**)&p_dw, g_dw);
    cudaGetSymbolAddress((void**)&p_qw, g_qw);
    cudaGetSymbolAddress((void**)&p_xdh, g_xdh);
    cudaGetSymbolAddress((void**)&p_xqh, g_xqh);
    cudaGetSymbolAddress((void**)&p_xdh2, g_xdh2);
    cudaGetSymbolAddress((void**)&p_xqh2, g_xqh2);
    cudaGetSymbolAddress((void**)&p_adh, g_adh);
    cudaGetSymbolAddress((void**)&p_aqh, g_aqh);
    cudaGetSymbolAddress((void**)&p_bdh, g_bdh);
    cudaGetSymbolAddress((void**)&p_bqh, g_bqh);
    cudaGetSymbolAddress((void**)&p_wh, g_wh);

    cudaFuncSetAttribute(gemm_info2, cudaFuncAttributeMaxDynamicSharedMemorySize, SMEM_DYN);
    cudaFuncSetAttribute(gemm_msg2,  cudaFuncAttributeMaxDynamicSharedMemorySize, SMEM_DYN);

    const uint32_t* wh_self = p_wh;
    const uint32_t* wh_dd   = p_wh + 1 * (size_t)DDIM * KU;
    const uint32_t* wh_qd   = p_wh + 2 * (size_t)DDIM * KU;
    const uint32_t* wh_qq   = p_wh + 3 * (size_t)DDIM * KU;
    const uint32_t* wh_dq   = p_wh + 4 * (size_t)DDIM * KU;

    // fused one-time prep (1 launch: weights + graphs + states)
    prep_all<<<320 + 5120 + 2048, 256>>>(
        W_self, W_dd, W_qd, W_qq, W_dq, p_wh,
        dd, dq, qq, qd, p_adh, p_aqh,
        d_node, q_node, p_xdh, p_xqh);

    uint32_t* xd = p_xdh;
    uint32_t* xq = p_xqh;
    uint32_t* xd_next = p_xdh2;
    uint32_t* xq_next = p_xqh2;

    for (int t = 0; t < 2; t++) {
        bool last = (t == 1);

        nw2<<<(BB * LDN + BB * LQN) / 8, 256>>>(xd, xq, W_nw, b_nw, p_dw, p_qw,
                                                out_dw + t * LDN, out_qw + t * LQN);

        gemm_info2<<<dim3(20, 4, BB), 256, SMEM_DYN>>>(
            wh_dd, wh_qd, wh_qq, wh_dq, xd, xq, p_dw, p_qw, p_bdh, p_bqh);

        gemm_msg2<<<dim3(8, 5, BB), 256, SMEM_DYN>>>(
            p_adh, p_aqh, xd, xq, p_bdh, p_bqh, wh_self, b_self,
            last ? out_dnode : nullptr, last ? nullptr : xd_next,
            last ? out_qnode : nullptr, last ? nullptr : xq_next);

        uint32_t* tmp;
        tmp = xd; xd = xd_next; xd_next = tmp;
        tmp = xq; xq = xq_next; xq_next = tmp;
    }
    (void)in_sizes; (void)n_in; (void)out_size;
}

// round 17
// speedup vs baseline: 1.0135x; 1.0135x over previous
#include <cuda_runtime.h>
#include <cuda_fp16.h>
#include <math.h>
#include <stdint.h>

#define BB 64
#define LDN 512
#define LQN 128
#define DDIM 512
#define KU   (DDIM/2)   // 256 uints (half2) per feature row
#define KG   320        // graph-part row width in uints: (512+128)/2
#define RSH  20         // smem row stride in uints: 16 data + 4 pad (conflict-free)
#define STAGE_B 15360u  // bytes per stage: A 128 rows (10240) + B 64 rows (5120)
#define SMEM_DYN (4 * 15360)

// ---------------- fp16 buffers (uint32 = half2, pairs along K) ----------------
__device__ uint32_t g_xdh[(size_t)BB*LDN*KU];    // d state (step input)
__device__ uint32_t g_xqh[(size_t)BB*LQN*KU];
__device__ uint32_t g_xdh2[(size_t)BB*LDN*KU];   // d state (next step)
__device__ uint32_t g_xqh2[(size_t)BB*LQN*KU];
__device__ uint32_t g_adh[(size_t)BB*LDN*KG];    // inv⊙[dd | dq] per d-row
__device__ uint32_t g_aqh[(size_t)BB*LQN*KG];    // inv⊙[qq | qd] per q-row
__device__ uint32_t g_bdh[(size_t)BB*DDIM*KG];   // [dd_info(256u) | dq_info(64u)] per n
__device__ uint32_t g_bqh[(size_t)BB*DDIM*KG];   // [qq_info(64u)  | qd_info(256u)] per n
__device__ uint32_t g_wh[5][(size_t)DDIM*KU];    // self, dd, qd, qq, dq
__device__ float g_dw[BB*LDN];
__device__ float g_qw[BB*LQN];

// ---------------- helpers ----------------
__device__ __forceinline__ uint32_t pk(float lo, float hi) {
    uint32_t u;
    asm("cvt.rn.f16x2.f32 %0, %1, %2;" : "=r"(u) : "f"(hi), "f"(lo));
    return u;
}
__device__ __forceinline__ void mma16(float* c, const uint32_t* a, const uint32_t* b) {
    asm volatile(
        "mma.sync.aligned.m16n8k16.row.col.f32.f16.f16.f32 "
        "{%0,%1,%2,%3}, {%4,%5,%6,%7}, {%8,%9}, {%0,%1,%2,%3};"
        : "+f"(c[0]), "+f"(c[1]), "+f"(c[2]), "+f"(c[3])
        : "r"(a[0]), "r"(a[1]), "r"(a[2]), "r"(a[3]), "r"(b[0]), "r"(b[1]));
}
__device__ __forceinline__ void ldm4(uint32_t* r, uint32_t addr) {
    asm volatile("ldmatrix.sync.aligned.m8n8.x4.shared.b16 {%0,%1,%2,%3}, [%4];"
                 : "=r"(r[0]), "=r"(r[1]), "=r"(r[2]), "=r"(r[3]) : "r"(addr));
}
__device__ __forceinline__ uint32_t smem_u32(const void* p) {
    uint32_t a;
    asm("{ .reg .u64 t; cvta.to.shared.u64 t, %1; cvt.u32.u64 %0, t; }" : "=r"(a) : "l"(p));
    return a;
}
__device__ __forceinline__ void cp16(uint32_t daddr, const uint32_t* g) {
    asm volatile("cp.async.cg.shared.global [%0], [%1], 16;"
                 :: "r"(daddr), "l"(__cvta_generic_to_global((void*)g)));
}
__device__ __forceinline__ void cpcommit() { asm volatile("cp.async.commit_group;"); }
__device__ __forceinline__ void cpwait0()  { asm volatile("cp.async.wait_group 0;"); }
__device__ __forceinline__ void cpwait2()  { asm volatile("cp.async.wait_group 2;"); }

// stage one (128-row A, 64-row B) x 32half tile pair into 4-stage ring via cp.async
__device__ __forceinline__ void issue4(uint32_t sb, int buf,
                                       const uint32_t* Asrc, int sA,
                                       const uint32_t* Bsrc, int sB,
                                       int kkU, int t) {
    uint32_t base = sb + (uint32_t)buf * STAGE_B;
    #pragma unroll
    for (int s = 0; s < 3; s++) {
        int idx = s * 256 + t;            // 768 16B copies: 512 A + 256 B
        int row = idx >> 2, c4 = idx & 3;
        if (row < 128) {
            uint32_t off = (uint32_t)((row * RSH + c4 * 4) * 4);
            cp16(base + off, Asrc + (size_t)row * sA + kkU + c4 * 4);
        } else {
            int r = row - 128;
            uint32_t off = 10240u + (uint32_t)((r * RSH + c4 * 4) * 4);
            cp16(base + off, Bsrc + (size_t)r * sB + kkU + c4 * 4);
        }
    }
    cpcommit();
}

// ldmatrix-based 32-K chunk compute (warp tile 32x32: 2 A frags x 2 B frags, 8 MMAs/kb)
__device__ __forceinline__ void compute_chunk(uint32_t aBase, uint32_t bBase,
                                              uint32_t so, float acc[2][4][4]) {
    #pragma unroll
    for (int kb = 0; kb < 2; kb++) {
        uint32_t a[2][4], bb[2][4];
        ldm4(a[0], aBase + so + (uint32_t)((kb * 8) * 4));
        ldm4(a[1], aBase + so + (uint32_t)((16 * RSH + kb * 8) * 4));
        ldm4(bb[0], bBase + so + (uint32_t)((kb * 8) * 4));
        ldm4(bb[1], bBase + so + (uint32_t)((16 * RSH + kb * 8) * 4));
        uint32_t b2[4][2] = {{bb[0][0], bb[0][2]}, {bb[0][1], bb[0][3]},
                             {bb[1][0], bb[1][2]}, {bb[1][1], bb[1][3]}};
        #pragma unroll
        for (int i = 0; i < 2; i++)
            #pragma unroll
            for (int j = 0; j < 4; j++)
                mma16(acc[i][j], a[i], b2[j]);
    }
}

// ---------------- fused prep: weight cvt + graph nb-cvt + state cvt, one launch ----------------
__device__ __forceinline__ void nbrow(const int* A1, const int* A2, int K1, int K2,
                                      int w, int lane, uint32_t* outA) {
    const int2* r1 = (const int2*)(A1 + (size_t)w * K1);
    const int2* r2 = (const int2*)(A2 + (size_t)w * K2);
    int Ku1 = K1 >> 1, Kt = (K1 + K2) >> 1;
    int s = 0;
    for (int u = lane; u < Ku1; u += 32) { int2 v = r1[u]; s += v.x + v.y; }
    for (int u = lane; u < Kt - Ku1; u += 32) { int2 v = r2[u]; s += v.x + v.y; }
    #pragma unroll
    for (int o = 16; o; o >>= 1) s += __shfl_xor_sync(0xFFFFFFFFu, s, o);
    float inv = 1.0f / ((s < 1) ? 1.0f : (float)s);
    uint32_t* orow = outA + (size_t)w * Kt;
    for (int u = lane; u < Kt; u += 32) {
        int2 v = (u < Ku1) ? r1[u] : r2[u - Ku1];
        orow[u] = pk(inv * (float)v.x, inv * (float)v.y);
    }
}

__global__ void prep_all(const float* __restrict__ w0, const float* __restrict__ w1,
                         const float* __restrict__ w2, const float* __restrict__ w3,
                         const float* __restrict__ w4, uint32_t* __restrict__ wdst,
                         const int* __restrict__ dd, const int* __restrict__ dq,
                         const int* __restrict__ qq, const int* __restrict__ qd,
                         uint32_t* __restrict__ outAd, uint32_t* __restrict__ outAq,
                         const float* __restrict__ dsrc, const float* __restrict__ qsrc,
                         uint32_t* __restrict__ xdh, uint32_t* __restrict__ xqh) {
    int bx = blockIdx.x;
    int t = threadIdx.x;
    if (bx < 320) {
        for (int i = bx * 256 + t; i < 5 * 65536; i += 320 * 256) {
            int which = i >> 16, off = i & 65535;
            const float* w = which == 0 ? w0 : which == 1 ? w1 : which == 2 ? w2
                           : which == 3 ? w3 : w4;
            float4 v = *(const float4*)(w + (size_t)off * 4);
            uint2 o = {pk(v.x, v.y), pk(v.z, v.w)};
            *(uint2*)(wdst + (size_t)i * 2) = o;
        }
    } else if (bx < 320 + 5120) {
        int w = (((bx - 320) * 256 + t)) >> 5;
        int lane = t & 31;
        int nd = BB * LDN;
        if (w < nd) nbrow(dd, dq, LDN, LQN, w, lane, outAd);
        else {
            w -= nd;
            if (w < BB * LQN) nbrow(qq, qd, LQN, LDN, w, lane, outAq);
        }
    } else {
        const int n4d = BB * LDN * DDIM / 4;
        const int n4t = n4d + BB * LQN * DDIM / 4;
        for (int i = (bx - 5440) * 256 + t; i < n4t; i += 2048 * 256) {
            const float* s;
            uint32_t* d;
            int off;
            if (i < n4d) { s = dsrc; d = xdh; off = i; }
            else         { s = qsrc; d = xqh; off = i - n4d; }
            float4 v = *(const float4*)(s + (size_t)off * 4);
            uint2 o = {pk(v.x, v.y), pk(v.z, v.w)};
            *(uint2*)(d + (size_t)off * 2) = o;
        }
    }
}

// ---------------- merged node weights: sigmoid(x . W_nw + b_nw) for d and q ----------------
__global__ void nw2(const uint32_t* __restrict__ xd, const uint32_t* __restrict__ xq,
                    const float* __restrict__ Wnw, const float* __restrict__ bnw,
                    float* __restrict__ dw, float* __restrict__ qw,
                    float* __restrict__ odw, float* __restrict__ oqw) {
    int w = (blockIdx.x * blockDim.x + threadIdx.x) >> 5;
    int lane = threadIdx.x & 31;
    const int nd = BB * LDN;
    const uint32_t* x;
    float *wbuf, *outw;
    int b, l, stride_b;
    if (w < nd) {
        x = xd + (size_t)w * KU; wbuf = dw; outw = odw;
        b = w >> 9; l = w & (LDN - 1); stride_b = 2 * LDN;
    } else {
        w -= nd;
        if (w >= BB * LQN) return;
        x = xq + (size_t)w * KU; wbuf = qw; outw = oqw;
        b = w >> 7; l = w & (LQN - 1); stride_b = 2 * LQN;
    }
    float s = 0.0f;
    #pragma unroll 4
    for (int u = lane; u < KU; u += 32) {
        float2 h = __half22float2(*(const __half2*)&x[u]);
        s += h.x * Wnw[2 * u] + h.y * Wnw[2 * u + 1];
    }
    #pragma unroll
    for (int o = 16; o; o >>= 1) s += __shfl_xor_sync(0xFFFFFFFFu, s, o);
    if (lane == 0) {
        float z = s + bnw[0];
        float v = 1.0f / (1.0f + expf(-z));
        wbuf[w] = v;
        outw[(size_t)b * stride_b + l] = v;
    }
}

// ---------------- fused info GEMM (all 4 weights, both node sets, one launch) ----------------
// blockIdx.x: 0-7 dd_info(j0=bx*64), 8-15 qd_info, 16-17 qq_info, 18-19 dq_info
__global__ void __launch_bounds__(256, 3)
gemm_info2(const uint32_t* __restrict__ wh_dd, const uint32_t* __restrict__ wh_qd,
           const uint32_t* __restrict__ wh_qq, const uint32_t* __restrict__ wh_dq,
           const uint32_t* __restrict__ xd, const uint32_t* __restrict__ xq,
           const float* __restrict__ dw, const float* __restrict__ qw,
           uint32_t* __restrict__ bdh, uint32_t* __restrict__ bqh) {
    extern __shared__ uint32_t smd[];
    uint32_t sb = smem_u32(smd);
    int t = threadIdx.x;
    int bx = blockIdx.x;
    int n0 = blockIdx.y * 128;
    int z = blockIdx.z;

    const uint32_t *Wsel, *X;
    const float* ws;
    uint32_t* ot;
    int L, j0;
    if (bx < 8)       { Wsel = wh_dd; X = xd; ws = dw; ot = bdh;       L = LDN; j0 = bx * 64; }
    else if (bx < 16) { Wsel = wh_qd; X = xd; ws = dw; ot = bqh + 64;  L = LDN; j0 = (bx - 8) * 64; }
    else if (bx < 18) { Wsel = wh_qq; X = xq; ws = qw; ot = bqh;       L = LQN; j0 = (bx - 16) * 64; }
    else              { Wsel = wh_dq; X = xq; ws = qw; ot = bdh + 256; L = LQN; j0 = (bx - 18) * 64; }

    const uint32_t* Ab = Wsel + (size_t)n0 * KU;
    const uint32_t* Bb = X + ((size_t)z * L + j0) * KU;
    ws += (size_t)z * L;
    ot += (size_t)z * DDIM * KG;

    int lane = t & 31, g = lane >> 2, tg = lane & 3;
    int wid = t >> 5;
    int wy = wid & 3, wx = wid >> 2;   // 4 M-groups x 2 N-groups, warp tile 32x32
    uint32_t aBase = sb + (uint32_t)(((wy * 32 + (lane & 15)) * RSH + (lane >> 4) * 4) * 4);
    uint32_t bBase = sb + 10240u +
                     (uint32_t)(((wx * 32 + (lane & 15)) * RSH + (lane >> 4) * 4) * 4);

    float acc[2][4][4];
    #pragma unroll
    for (int i = 0; i < 2; i++)
        #pragma unroll
        for (int j = 0; j < 4; j++)
            #pragma unroll
            for (int k = 0; k < 4; k++) acc[i][j][k] = 0.0f;

    issue4(sb, 0, Ab, KU, Bb, KU, 0, t);
    issue4(sb, 1, Ab, KU, Bb, KU, 16, t);
    issue4(sb, 2, Ab, KU, Bb, KU, 32, t);
    for (int c = 0; c < 16; c++) {
        if (c + 3 < 16) cpwait2(); else cpwait0();
        __syncthreads();
        if (c + 3 < 16) issue4(sb, (c + 3) & 3, Ab, KU, Bb, KU, (c + 3) * 16, t);
        compute_chunk(aBase, bBase, (uint32_t)(c & 3) * STAGE_B, acc);
    }

    #pragma unroll
    for (int i = 0; i < 2; i++) {
        int R0 = n0 + wy * 32 + i * 16 + g;
        int R1 = R0 + 8;
        #pragma unroll
        for (int j = 0; j < 4; j++) {
            int C = j0 + wx * 32 + j * 8 + 2 * tg;
            float2 s = *(const float2*)&ws[C];
            ot[(size_t)R0 * KG + (C >> 1)] = pk(acc[i][j][0] * s.x, acc[i][j][1] * s.y);
            ot[(size_t)R1 * KG + (C >> 1)] = pk(acc[i][j][2] * s.x, acc[i][j][3] * s.y);
        }
    }
}

// ---------------- fused message+self GEMM (d and q sides in one launch) ----------------
// blockIdx.y 0-3: d-side row blocks; 4: q-side (M=128). blockIdx.x: n-tile of 64.
__global__ void __launch_bounds__(256, 3)
gemm_msg2(const uint32_t* __restrict__ adh, const uint32_t* __restrict__ aqh,
          const uint32_t* __restrict__ xd, const uint32_t* __restrict__ xq,
          const uint32_t* __restrict__ bdh, const uint32_t* __restrict__ bqh,
          const uint32_t* __restrict__ wself, const float* __restrict__ bias,
          float* __restrict__ outd, uint32_t* __restrict__ outHd,
          float* __restrict__ outq, uint32_t* __restrict__ outHq) {
    int z = blockIdx.z;
    int by = blockIdx.y;
    const uint32_t *Ag, *Xh, *Bg;
    float* out;
    uint32_t* outH;
    int M, r0;
    if (by < 4) { Ag = adh; Xh = xd; Bg = bdh; out = outd; outH = outHd; M = LDN; r0 = by * 128; }
    else        { Ag = aqh; Xh = xq; Bg = bqh; out = outq; outH = outHq; M = LQN; r0 = 0; }
    Ag += (size_t)z * M * KG;
    Xh += (size_t)z * M * KU;
    Bg += (size_t)z * DDIM * KG;
    if (out)  out  += (size_t)z * M * DDIM;
    if (outH) outH += (size_t)z * M * KU;

    extern __shared__ uint32_t smd[];
    uint32_t sb = smem_u32(smd);
    int t = threadIdx.x;
    int c0 = blockIdx.x * 64;
    const uint32_t* Ab1 = Ag + (size_t)r0 * KG;
    const uint32_t* Ab2 = Xh + (size_t)r0 * KU;
    const uint32_t* Bb1 = Bg + (size_t)c0 * KG;
    const uint32_t* Bb2 = wself + (size_t)c0 * KU;

    int lane = t & 31, g = lane >> 2, tg = lane & 3;
    int wid = t >> 5;
    int wy = wid & 3, wx = wid >> 2;   // 4 M-groups x 2 N-groups, warp tile 32x32
    uint32_t aBase = sb + (uint32_t)(((wy * 32 + (lane & 15)) * RSH + (lane >> 4) * 4) * 4);
    uint32_t bBase = sb + 10240u +
                     (uint32_t)(((wx * 32 + (lane & 15)) * RSH + (lane >> 4) * 4) * 4);

    float acc[2][4][4];
    #pragma unroll
    for (int i = 0; i < 2; i++)
        #pragma unroll
        for (int j = 0; j < 4; j++)
            #pragma unroll
            for (int k = 0; k < 4; k++) acc[i][j][k] = 0.0f;

    const int nch = 36;  // 20 graph chunks + 16 feature chunks
    issue4(sb, 0, Ab1, KG, Bb1, KG, 0, t);
    issue4(sb, 1, Ab1, KG, Bb1, KG, 16, t);
    issue4(sb, 2, Ab1, KG, Bb1, KG, 32, t);
    for (int c = 0; c < nch; c++) {
        if (c + 3 < nch) cpwait2(); else cpwait0();
        __syncthreads();
        if (c + 3 < nch) {
            int kkU = (c + 3) * 16;
            if (kkU < KG) issue4(sb, (c + 3) & 3, Ab1, KG, Bb1, KG, kkU, t);
            else          issue4(sb, (c + 3) & 3, Ab2, KU, Bb2, KU, kkU - KG, t);
        }
        compute_chunk(aBase, bBase, (uint32_t)(c & 3) * STAGE_B, acc);
    }

    #pragma unroll
    for (int i = 0; i < 2; i++) {
        int R0 = r0 + wy * 32 + i * 16 + g;
        int R1 = R0 + 8;
        #pragma unroll
        for (int j = 0; j < 4; j++) {
            int C = c0 + wx * 32 + j * 8 + 2 * tg;
            float2 bz = *(const float2*)&bias[C];
            float2 v0, v1;
            v0.x = fmaxf(acc[i][j][0] + bz.x, 0.0f);
            v0.y = fmaxf(acc[i][j][1] + bz.y, 0.0f);
            v1.x = fmaxf(acc[i][j][2] + bz.x, 0.0f);
            v1.y = fmaxf(acc[i][j][3] + bz.y, 0.0f);
            if (out) {
                *(float2*)&out[(size_t)R0 * DDIM + C] = v0;
                *(float2*)&out[(size_t)R1 * DDIM + C] = v1;
            }
            if (outH) {
                outH[(size_t)R0 * KU + (C >> 1)] = pk(v0.x, v0.y);
                outH[(size_t)R1 * KU + (C >> 1)] = pk(v1.x, v1.y);
            }
        }
    }
}

// ---------------- host orchestration ----------------
extern "C" void kernel_launch(void* const* d_in, const int* in_sizes, int n_in,
                              void* d_out_, int out_size) {
    const float* d_node = (const float*)d_in[0];
    const float* q_node = (const float*)d_in[1];
    const int*   qq     = (const int*)d_in[2];
    const int*   dq     = (const int*)d_in[3];
    const int*   dd     = (const int*)d_in[4];
    const int*   qd     = (const int*)d_in[5];
    const float* W_nw   = (const float*)d_in[6];
    const float* b_nw   = (const float*)d_in[7];
    const float* W_self = (const float*)d_in[8];
    const float* b_self = (const float*)d_in[9];
    const float* W_dd   = (const float*)d_in[10];
    const float* W_qq   = (const float*)d_in[11];
    const float* W_dq   = (const float*)d_in[12];
    const float* W_qd   = (const float*)d_in[13];

    float* out = (float*)d_out_;
    float* out_dnode = out;
    float* out_qnode = out + (size_t)BB * LDN * DDIM;
    float* out_dw    = out_qnode + (size_t)BB * LQN * DDIM;
    float* out_qw    = out_dw + (size_t)BB * 2 * LDN;

    float *p_dw, *p_qw;
    uint32_t *p_xdh, *p_xqh, *p_xdh2, *p_xqh2, *p_adh, *p_aqh, *p_bdh, *p_bqh, *p_wh;
    cudaGetSymbolAddress((void**)&p_dw, g_dw);
    cudaGetSymbolAddress((void**)&p_qw, g_qw);
    cudaGetSymbolAddress((void**)&p_xdh, g_xdh);
    cudaGetSymbolAddress((void**)&p_xqh, g_xqh);
    cudaGetSymbolAddress((void**)&p_xdh2, g_xdh2);
    cudaGetSymbolAddress((void**)&p_xqh2, g_xqh2);
    cudaGetSymbolAddress((void**)&p_adh, g_adh);
    cudaGetSymbolAddress((void**)&p_aqh, g_aqh);
    cudaGetSymbolAddress((void**)&p_bdh, g_bdh);
    cudaGetSymbolAddress((void**)&p_bqh, g_bqh);
    cudaGetSymbolAddress((void**)&p_wh, g_wh);

    cudaFuncSetAttribute(gemm_info2, cudaFuncAttributeMaxDynamicSharedMemorySize, SMEM_DYN);
    cudaFuncSetAttribute(gemm_msg2,  cudaFuncAttributeMaxDynamicSharedMemorySize, SMEM_DYN);

    const uint32_t* wh_self = p_wh;
    const uint32_t* wh_dd   = p_wh + 1 * (size_t)DDIM * KU;
    const uint32_t* wh_qd   = p_wh + 2 * (size_t)DDIM * KU;
    const uint32_t* wh_qq   = p_wh + 3 * (size_t)DDIM * KU;
    const uint32_t* wh_dq   = p_wh + 4 * (size_t)DDIM * KU;

    // fused one-time prep (1 launch: weights + graphs + states)
    prep_all<<<320 + 5120 + 2048, 256>>>(
        W_self, W_dd, W_qd, W_qq, W_dq, p_wh,
        dd, dq, qq, qd, p_adh, p_aqh,
        d_node, q_node, p_xdh, p_xqh);

    uint32_t* xd = p_xdh;
    uint32_t* xq = p_xqh;
    uint32_t* xd_next = p_xdh2;
    uint32_t* xq_next = p_xqh2;

    for (int t = 0; t < 2; t++) {
        bool last = (t == 1);

        nw2<<<(BB * LDN + BB * LQN) / 8, 256>>>(xd, xq, W_nw, b_nw, p_dw, p_qw,
                                                out_dw + t * LDN, out_qw + t * LQN);

        gemm_info2<<<dim3(20, 4, BB), 256, SMEM_DYN>>>(
            wh_dd, wh_qd, wh_qq, wh_dq, xd, xq, p_dw, p_qw, p_bdh, p_bqh);

        gemm_msg2<<<dim3(8, 5, BB), 256, SMEM_DYN>>>(
            p_adh, p_aqh, xd, xq, p_bdh, p_bqh, wh_self, b_self,
            last ? out_dnode : nullptr, last ? nullptr : xd_next,
            last ? out_qnode : nullptr, last ? nullptr : xq_next);

        uint32_t* tmp;
        tmp = xd; xd = xd_next; xd_next = tmp;
        tmp = xq; xq = xq_next; xq_next = tmp;
    }
    (void)in_sizes; (void)n_in; (void)out_size;
}